// round 6
// baseline (speedup 1.0000x reference)
#include <cuda_runtime.h>
#include <cstdint>

// ---------------------------------------------------------------------------
// TreeCnnLayer: y[b,l,o] = relu( sum_{k=0..3} sum_i x[b, idx[l,k], i] * mask[k,i,o] + bias[127] )
// Gathered GEMM: M=131072, K=512, N=128.  mma.sync tf32 (plain sm_100 target).
// R6: 256 thr / 8 warps (32x64 warp tiles, R3's proven occupancy) + ldmatrix.x4
//     loads (R5's proven L1 win) + 3-stage cp.async ring.
// ---------------------------------------------------------------------------

#define BATCH   16
#define NROWS   8192
#define TILE_M  128
#define NTILES  (NROWS / TILE_M)    // 64
#define BK      32
#define NCHUNK  16                  // 512 / 32
#define RPITCH  144                 // smem row pitch in bytes (36 floats)

#define STAGE_B   (128 * RPITCH)    // 18432 B per A (or BT) stage
#define SIDX_B    2048
#define NSTAGE    3
#define SMEM_TOTAL (SIDX_B + 2 * NSTAGE * STAGE_B)   // 112640

// W transposed + tf32-prerounded: g_WT[k][o][i] = rna_tf32(mask[k][i][o])
__device__ float g_WT[4 * 128 * 128];

__device__ __forceinline__ uint32_t smem_u32(const void* p) {
    uint32_t a;
    asm("{ .reg .u64 t; cvta.to.shared.u64 t, %1; cvt.u32.u64 %0, t; }" : "=r"(a) : "l"(p));
    return a;
}
__device__ __forceinline__ uint32_t f2tf32(float f) {
    uint32_t u;
    asm("cvt.rna.tf32.f32 %0, %1;" : "=r"(u) : "f"(f));
    return u;
}
__device__ __forceinline__ void cp_async16_cg(uint32_t dst, const void* src) {
    asm volatile("cp.async.cg.shared.global [%0], [%1], 16;" :: "r"(dst), "l"(src));
}
__device__ __forceinline__ void cp_async16_ca(uint32_t dst, const void* src) {
    asm volatile("cp.async.ca.shared.global [%0], [%1], 16;" :: "r"(dst), "l"(src));
}
__device__ __forceinline__ void ldsm_x4(uint32_t* r, uint32_t addr) {
    asm volatile("ldmatrix.sync.aligned.m8n8.x4.shared.b16 {%0,%1,%2,%3}, [%4];"
                 : "=r"(r[0]), "=r"(r[1]), "=r"(r[2]), "=r"(r[3]) : "r"(addr));
}
__device__ __forceinline__ void mma_tf32(float* d, const uint32_t* a, const uint32_t* b) {
    asm volatile(
        "mma.sync.aligned.m16n8k8.row.col.f32.tf32.tf32.f32 "
        "{%0,%1,%2,%3}, {%4,%5,%6,%7}, {%8,%9}, {%0,%1,%2,%3};"
        : "+f"(d[0]), "+f"(d[1]), "+f"(d[2]), "+f"(d[3])
        : "r"(a[0]), "r"(a[1]), "r"(a[2]), "r"(a[3]), "r"(b[0]), "r"(b[1]));
}

// ---------------- prep: transpose + round weights ----------------
__global__ void prep_w_kernel(const float* __restrict__ mask) {
    int t = blockIdx.x * blockDim.x + threadIdx.x;      // 65536
    int k = t >> 14, o = (t >> 7) & 127, i = t & 127;   // write-coalesced over i
    g_WT[t] = __uint_as_float(f2tf32(mask[(k << 14) + (i << 7) + o]));
}

// ---------------- main kernel ----------------
__global__ void __launch_bounds__(256, 2)
tree_gemm(const float* __restrict__ x, const float* __restrict__ bias,
          const int* __restrict__ itab32, float* __restrict__ out)
{
    extern __shared__ char smem[];
    int* sIdx = (int*)smem;
    const uint32_t sbase = smem_u32(smem);
    uint32_t aBuf[NSTAGE], bBuf[NSTAGE];
    #pragma unroll
    for (int s = 0; s < NSTAGE; s++) {
        aBuf[s] = sbase + SIDX_B + s * STAGE_B;
        bBuf[s] = sbase + SIDX_B + (NSTAGE + s) * STAGE_B;
    }

    const int tid  = threadIdx.x;
    const int lane = tid & 31;
    const int wid  = tid >> 5;        // 8 warps: 4M x 2N
    const int wm   = wid >> 1;        // 0..3
    const int wn   = wid & 1;         // 0..1
    const int gr   = lane >> 2;
    const int qc   = lane & 3;
    const int b    = blockIdx.y;
    const int V    = blockIdx.x * TILE_M;

    // index dtype autodetect (int64 LE: word[1]=hi(tab[0,0])=0; int32: tab[0,1]=8191)
    const int istride = (itab32[1] == 0) ? 2 : 1;

    #pragma unroll
    for (int j = tid; j < 512; j += 256) {
        int k = j >> 7, r = j & 127;
        sIdx[j] = itab32[(size_t)(((V + r) << 2) + k) * istride];
    }
    __syncthreads();

    const char* xb = (const char*)(x + (size_t)b * NROWS * 128);

    // ldmatrix per-thread invariant offsets (matrix id 0..3, row-in-matrix 0..7):
    // x4 tile covers 16 rows x 8 k-floats: m0/m1 = rows0-7 k0-3/k4-7, m2/m3 = rows8-15.
    const int m_id = lane >> 3, r_in = lane & 7;
    const uint32_t ldsmOff = (uint32_t)((r_in + ((m_id & 2) << 2)) * RPITCH + (m_id & 1) * 16);
    const uint32_t aOff = (uint32_t)(wm * 32 * RPITCH) + ldsmOff;
    const uint32_t bOff = (uint32_t)(wn * 64 * RPITCH) + ldsmOff;

    auto load_chunk = [&](int c, int st) {
        const int k  = c >> 2;
        const int c0 = (c & 3) * BK;
        // A: gathered rows, 128 x 32 floats; 1024 16B segs, 4 per thread
        #pragma unroll
        for (int i = 0; i < 4; i++) {
            int seg = tid + (i << 8);
            int r = seg >> 3, cs = seg & 7;
            int g = sIdx[(k << 7) + r];
            cp_async16_cg(aBuf[st] + r * RPITCH + cs * 16,
                          xb + (((size_t)g << 7) + c0 + (cs << 2)) * 4);
        }
        // BT: 128 o-rows x 32 k-floats from g_WT[k][o][c0..c0+31]
        const char* wb = (const char*)g_WT + (((size_t)k << 14) + c0) * 4;
        #pragma unroll
        for (int i = 0; i < 4; i++) {
            int seg = tid + (i << 8);
            int r = seg >> 3, cs = seg & 7;
            cp_async16_ca(bBuf[st] + r * RPITCH + cs * 16,
                          wb + ((size_t)(r << 7) + (cs << 2)) * 4);
        }
        asm volatile("cp.async.commit_group;");
    };

    float acc[2][8][4];
    #pragma unroll
    for (int mf = 0; mf < 2; mf++)
        #pragma unroll
        for (int nf = 0; nf < 8; nf++)
            #pragma unroll
            for (int q = 0; q < 4; q++) acc[mf][nf][q] = 0.0f;

    load_chunk(0, 0);
    load_chunk(1, 1);

    for (int c = 0; c < NCHUNK; c++) {
        const int st = c % NSTAGE;
        if (c + 2 < NCHUNK) load_chunk(c + 2, (c + 2) % NSTAGE);

        if (c < NCHUNK - 2)      asm volatile("cp.async.wait_group 2;");
        else if (c == NCHUNK - 2) asm volatile("cp.async.wait_group 1;");
        else                      asm volatile("cp.async.wait_group 0;");
        __syncthreads();

        const uint32_t aB = aBuf[st] + aOff;
        const uint32_t bB = bBuf[st] + bOff;

        #pragma unroll
        for (int ks = 0; ks < 4; ks++) {
            const uint32_t ko = (uint32_t)(ks * 32);
            // A: 2x LDSM.x4 (rows wm*32..+31), cvt.rna to tf32
            uint32_t a[2][4];
            #pragma unroll
            for (int mf = 0; mf < 2; mf++) {
                uint32_t r[4];
                ldsm_x4(r, aB + (uint32_t)(mf * 16 * RPITCH) + ko);
                a[mf][0] = f2tf32(__uint_as_float(r[0]));
                a[mf][1] = f2tf32(__uint_as_float(r[2]));
                a[mf][2] = f2tf32(__uint_as_float(r[1]));
                a[mf][3] = f2tf32(__uint_as_float(r[3]));
            }
            // B (pre-rounded): 4x LDSM.x4, each covers 2 nf
            uint32_t bb[8][2];
            #pragma unroll
            for (int p = 0; p < 4; p++) {
                uint32_t r[4];
                ldsm_x4(r, bB + (uint32_t)(p * 16 * RPITCH) + ko);
                bb[2 * p][0]     = r[0];
                bb[2 * p][1]     = r[1];
                bb[2 * p + 1][0] = r[2];
                bb[2 * p + 1][1] = r[3];
            }
            #pragma unroll
            for (int mf = 0; mf < 2; mf++)
                #pragma unroll
                for (int nf = 0; nf < 8; nf++)
                    mma_tf32(acc[mf][nf], a[mf], bb[nf]);
        }
        __syncthreads();
    }

    // ---- epilogue: +bias[127], relu, store ----
    const float bv = bias[127];
    float* ob = out + ((size_t)b * NROWS + V + wm * 32) * 128 + wn * 64;

    #pragma unroll
    for (int mf = 0; mf < 2; mf++) {
        #pragma unroll
        for (int nf = 0; nf < 8; nf++) {
            int row = mf * 16 + gr;
            int col = nf * 8 + 2 * qc;
            float2 v0, v1;
            v0.x = fmaxf(acc[mf][nf][0] + bv, 0.0f);
            v0.y = fmaxf(acc[mf][nf][1] + bv, 0.0f);
            v1.x = fmaxf(acc[mf][nf][2] + bv, 0.0f);
            v1.y = fmaxf(acc[mf][nf][3] + bv, 0.0f);
            *(float2*)(ob + (size_t)row * 128 + col)       = v0;
            *(float2*)(ob + (size_t)(row + 8) * 128 + col) = v1;
        }
    }
}

// ---------------- launch ----------------
extern "C" void kernel_launch(void* const* d_in, const int* in_sizes, int n_in,
                              void* d_out, int out_size)
{
    const float* x = nullptr;
    const float* mask = nullptr;
    const float* bias = nullptr;
    const int*   itab = nullptr;
    for (int i = 0; i < n_in; i++) {
        switch (in_sizes[i]) {
            case 16777216: x    = (const float*)d_in[i]; break;
            case 65536:    mask = (const float*)d_in[i]; break;
            case 128:      bias = (const float*)d_in[i]; break;
            case 32768:    itab = (const int*)d_in[i];   break;
            default: break;
        }
    }
    float* out = (float*)d_out;

    cudaFuncSetAttribute(tree_gemm,
                         cudaFuncAttributeMaxDynamicSharedMemorySize, SMEM_TOTAL);

    prep_w_kernel<<<256, 256>>>(mask);

    dim3 grid(NTILES, BATCH);
    tree_gemm<<<grid, 256, SMEM_TOTAL>>>(x, bias, itab, out);
}

// round 8
// speedup vs baseline: 1.1891x; 1.1891x over previous
#include <cuda_runtime.h>
#include <cstdint>

// ---------------------------------------------------------------------------
// TreeCnnLayer: y[b,l,o] = relu( sum_{k=0..3} sum_i x[b, idx[l,k], i] * mask[k,i,o] + bias[127] )
// Gathered GEMM: M=131072, K=512, N=128.  mma.sync tf32 (plain sm_100 target).
// R8 (= R7 resubmit after infra failure): R3's proven config (256 thr, 4Mx2N
//     warps of 32x64, plain LDS, 121 regs) + 3-stage cp.async ring with ONE
//     __syncthreads per chunk and register-rotated stage offsets.
// ---------------------------------------------------------------------------

#define BATCH   16
#define NROWS   8192
#define TILE_M  128
#define NTILES  (NROWS / TILE_M)    // 64
#define BK      32
#define NCHUNK  16                  // 512 / 32
#define ASTR    36                  // A smem row stride (floats)
#define BSTR    136                 // B smem row stride (floats)

#define A_STAGE_B  18432            // 128 rows * 144 B
#define B_STAGE_B  17408            // 32 rows * 544 B
#define SIDX_B     2048
#define NSTAGE     3
#define SMEM_TOTAL (SIDX_B + NSTAGE * (A_STAGE_B + B_STAGE_B))   // 109568

// Weights pre-rounded to tf32 (rna) once, so the hot loop needs no cvt on B.
__device__ float g_Wrnd[4 * 128 * 128];

__device__ __forceinline__ uint32_t smem_u32(const void* p) {
    uint32_t a;
    asm("{ .reg .u64 t; cvta.to.shared.u64 t, %1; cvt.u32.u64 %0, t; }" : "=r"(a) : "l"(p));
    return a;
}
__device__ __forceinline__ uint32_t f2tf32(float f) {
    uint32_t u;
    asm("cvt.rna.tf32.f32 %0, %1;" : "=r"(u) : "f"(f));
    return u;
}
__device__ __forceinline__ void cp_async16_cg(uint32_t dst, const void* src) {
    asm volatile("cp.async.cg.shared.global [%0], [%1], 16;" :: "r"(dst), "l"(src));
}
__device__ __forceinline__ void cp_async16_ca(uint32_t dst, const void* src) {
    asm volatile("cp.async.ca.shared.global [%0], [%1], 16;" :: "r"(dst), "l"(src));
}
__device__ __forceinline__ void mma_tf32(float* d, const uint32_t* a, const uint32_t* b) {
    asm volatile(
        "mma.sync.aligned.m16n8k8.row.col.f32.tf32.tf32.f32 "
        "{%0,%1,%2,%3}, {%4,%5,%6,%7}, {%8,%9}, {%0,%1,%2,%3};"
        : "+f"(d[0]), "+f"(d[1]), "+f"(d[2]), "+f"(d[3])
        : "r"(a[0]), "r"(a[1]), "r"(a[2]), "r"(a[3]), "r"(b[0]), "r"(b[1]));
}

// ---------------- prep: round weights to tf32 ----------------
__global__ void prep_w_kernel(const float* __restrict__ mask) {
    int t = blockIdx.x * blockDim.x + threadIdx.x;     // 65536 threads
    g_Wrnd[t] = __uint_as_float(f2tf32(mask[t]));
}

// ---------------- main kernel ----------------
__global__ void __launch_bounds__(256, 2)
tree_gemm(const float* __restrict__ x, const float* __restrict__ bias,
          const int* __restrict__ itab32, float* __restrict__ out)
{
    extern __shared__ char smem[];
    int* sIdx = (int*)smem;
    const uint32_t sbase = smem_u32(smem);

    const int tid  = threadIdx.x;
    const int lane = tid & 31;
    const int wid  = tid >> 5;          // 8 warps: 4M x 2N
    const int wm   = wid >> 1;          // 0..3
    const int wn   = wid & 1;           // 0..1
    const int gr   = lane >> 2;
    const int qc   = lane & 3;
    const int b    = blockIdx.y;
    const int V    = blockIdx.x * TILE_M;

    // index dtype autodetect (int64 LE: word[1]=hi(tab[0,0])=0; int32: tab[0,1]=8191)
    const int istride = (itab32[1] == 0) ? 2 : 1;
    const float bv = bias[127];

    #pragma unroll
    for (int j = tid; j < 512; j += 256) {
        int k = j >> 7, r = j & 127;
        sIdx[j] = itab32[(size_t)(((V + r) << 2) + k) * istride];
    }
    __syncthreads();

    const char* xb = (const char*)(x + (size_t)b * NROWS * 128);

    // Byte offsets (relative to smem[]) of the three A / B stages; rotated in regs.
    uint32_t aCur = SIDX_B;
    uint32_t aNxt = SIDX_B + A_STAGE_B;
    uint32_t aPre = SIDX_B + 2 * A_STAGE_B;
    uint32_t bCur = SIDX_B + 3 * A_STAGE_B;
    uint32_t bNxt = bCur + B_STAGE_B;
    uint32_t bPre = bCur + 2 * B_STAGE_B;

    // ---- chunk loader: chunk c (k = c>>2, c0 = (c&3)*32) into stage offsets ----
    auto load_chunk = [&](int c, uint32_t aOff, uint32_t bOff) {
        const int k  = c >> 2;
        const int c0 = (c & 3) * BK;
        const uint32_t aB = sbase + aOff;
        const uint32_t bB = sbase + bOff;
        // A: 128 rows x 32 floats, 16B segs; seg = r*8 + cs
        #pragma unroll
        for (int i = 0; i < 4; i++) {
            int seg = tid + i * 256;
            int r = seg >> 3, cs = seg & 7;
            int g = sIdx[(k << 7) + r];
            cp_async16_cg(aB + r * 144 + cs * 16,
                          xb + (((size_t)g << 7) + c0 + (cs << 2)) * 4);
        }
        // B: 32 rows (k-dim) x 128 floats; seg = r*32 + cs
        const char* wb = (const char*)g_Wrnd + ((size_t)((k << 7) + c0) << 9);
        #pragma unroll
        for (int i = 0; i < 4; i++) {
            int seg = tid + i * 256;
            int r = seg >> 5, cs = seg & 31;
            cp_async16_ca(bB + r * 544 + cs * 16, wb + ((r << 7) + (cs << 2)) * 4);
        }
        asm volatile("cp.async.commit_group;");
    };

    float acc[2][8][4];
    #pragma unroll
    for (int mf = 0; mf < 2; mf++)
        #pragma unroll
        for (int nf = 0; nf < 8; nf++)
            #pragma unroll
            for (int q = 0; q < 4; q++) acc[mf][nf][q] = 0.0f;

    load_chunk(0, aCur, bCur);
    load_chunk(1, aNxt, bNxt);

    for (int c = 0; c < NCHUNK; c++) {
        // Need chunk c complete; chunk c+1 may remain in flight.
        if (c < NCHUNK - 1) asm volatile("cp.async.wait_group 1;");
        else                asm volatile("cp.async.wait_group 0;");
        // Single barrier per chunk: also fences last iteration's stage reads,
        // making it safe to refill stage (c+2)%3 == (c-1)%3 right after.
        __syncthreads();

        if (c + 2 < NCHUNK) load_chunk(c + 2, aPre, bPre);

        const float* A = (const float*)(smem + aCur);
        const float* B = (const float*)(smem + bCur);

        #pragma unroll
        for (int ks = 0; ks < 4; ks++) {
            const int kc = ks << 3;
            // A fragments (warp rows wm*32 .. +31): cvt.rna to tf32
            uint32_t a[2][4];
            #pragma unroll
            for (int mf = 0; mf < 2; mf++) {
                const float* ap = A + (wm * 32 + mf * 16 + gr) * ASTR + kc + qc;
                a[mf][0] = f2tf32(ap[0]);
                a[mf][1] = f2tf32(ap[8 * ASTR]);
                a[mf][2] = f2tf32(ap[4]);
                a[mf][3] = f2tf32(ap[8 * ASTR + 4]);
            }
            // B fragments (pre-rounded): cols wn*64 .. +63
            uint32_t bb[8][2];
            #pragma unroll
            for (int nf = 0; nf < 8; nf++) {
                const float* bp = B + (kc + qc) * BSTR + wn * 64 + nf * 8 + gr;
                bb[nf][0] = __float_as_uint(bp[0]);
                bb[nf][1] = __float_as_uint(bp[4 * BSTR]);
            }
            #pragma unroll
            for (int mf = 0; mf < 2; mf++)
                #pragma unroll
                for (int nf = 0; nf < 8; nf++)
                    mma_tf32(acc[mf][nf], a[mf], bb[nf]);
        }

        // rotate stages: (cur, nxt, pre) <- (nxt, pre, cur)
        uint32_t t;
        t = aCur; aCur = aNxt; aNxt = aPre; aPre = t;
        t = bCur; bCur = bNxt; bNxt = bPre; bPre = t;
    }

    // ---- epilogue: +bias[127], relu, store ----
    float* ob = out + ((size_t)b * NROWS + V + wm * 32) * 128 + wn * 64;

    #pragma unroll
    for (int mf = 0; mf < 2; mf++) {
        #pragma unroll
        for (int nf = 0; nf < 8; nf++) {
            int row = mf * 16 + gr;
            int col = nf * 8 + 2 * qc;
            float2 v0, v1;
            v0.x = fmaxf(acc[mf][nf][0] + bv, 0.0f);
            v0.y = fmaxf(acc[mf][nf][1] + bv, 0.0f);
            v1.x = fmaxf(acc[mf][nf][2] + bv, 0.0f);
            v1.y = fmaxf(acc[mf][nf][3] + bv, 0.0f);
            *(float2*)(ob + (size_t)row * 128 + col)       = v0;
            *(float2*)(ob + (size_t)(row + 8) * 128 + col) = v1;
        }
    }
}

// ---------------- launch ----------------
extern "C" void kernel_launch(void* const* d_in, const int* in_sizes, int n_in,
                              void* d_out, int out_size)
{
    const float* x = nullptr;
    const float* mask = nullptr;
    const float* bias = nullptr;
    const int*   itab = nullptr;
    for (int i = 0; i < n_in; i++) {
        switch (in_sizes[i]) {
            case 16777216: x    = (const float*)d_in[i]; break;
            case 65536:    mask = (const float*)d_in[i]; break;
            case 128:      bias = (const float*)d_in[i]; break;
            case 32768:    itab = (const int*)d_in[i];   break;
            default: break;
        }
    }
    float* out = (float*)d_out;

    cudaFuncSetAttribute(tree_gemm,
                         cudaFuncAttributeMaxDynamicSharedMemorySize, SMEM_TOTAL);

    prep_w_kernel<<<256, 256>>>(mask);

    dim3 grid(NTILES, BATCH);
    tree_gemm<<<grid, 256, SMEM_TOTAL>>>(x, bias, itab, out);
}